// round 7
// baseline (speedup 1.0000x reference)
#include <cuda_runtime.h>
#include <cuda_bf16.h>

typedef unsigned long long ULL;

// ---------------- f32x2 packed helpers (sm_100+) ----------------
__device__ __forceinline__ ULL ffma2(ULL a, ULL b, ULL c) {
    ULL d;
    asm("fma.rn.f32x2 %0, %1, %2, %3;" : "=l"(d) : "l"(a), "l"(b), "l"(c));
    return d;
}
__device__ __forceinline__ ULL fadd2(ULL a, ULL b) {
    ULL d;
    asm("add.rn.f32x2 %0, %1, %2;" : "=l"(d) : "l"(a), "l"(b));
    return d;
}
__device__ __forceinline__ ULL dup2(float w) {
    unsigned u = __float_as_uint(w);
    ULL d;
    asm("mov.b64 %0, {%1, %1};" : "=l"(d) : "r"(u));
    return d;
}
__device__ __forceinline__ ULL pack2(float lo, float hi) {
    ULL d;
    unsigned a = __float_as_uint(lo), b = __float_as_uint(hi);
    asm("mov.b64 %0, {%1, %2};" : "=l"(d) : "r"(a), "r"(b));
    return d;
}
__device__ __forceinline__ void unpack2(ULL v, float& lo, float& hi) {
    unsigned a, b;
    asm("mov.b64 {%0, %1}, %2;" : "=r"(a), "=r"(b) : "l"(v));
    lo = __uint_as_float(a);
    hi = __uint_as_float(b);
}

// Weights pre-scaled by C = 2*log2(e): accumulator holds u = 2*log2(e)*a.
// tanh(a) = 1 - 2/(exp2(u)+1). Proven path: rel_err 2.3e-7.
__device__ __forceinline__ float tanh_from_scaled(float u) {
    float e;
    asm("ex2.approx.f32 %0, %1;" : "=f"(e) : "f"(u));
    float r;
    asm("rcp.approx.f32 %0, %1;" : "=f"(r) : "f"(e + 1.0f));
    return fmaf(-2.0f, r, 1.0f);
}

// ---------------- config ----------------
// B=4096, T=2048, F=8, H=32, O=8
// One 32-thread block = one warp = 8 batch rows = 4 f32x2 pairs, as two
// independent GROUPS of 2 pairs. Half-warp split within each group (lanes
// 0-15 pair {g,0}, lanes 16-31 pair {g,1}); each lane computes h rows llo
// and llo+16, so W_hh rows llo/llo+16 in registers serve BOTH groups.
// Per step the warp issues G0's rt-bound FMA block then G1's; G0's
// tanh/STS tail overlaps G1's FMA issue via the scoreboard -> intra-warp
// latency hiding that R4-R6 showed the 2-warp arbiter does not deliver.
#define TT    2048
#define FF    8
#define HH    32
#define OO    8
#define CHUNK 8       // timesteps of x staged per SMEM refill
#define NP    4       // pairs per warp
#define HPAD  34      // ULL stride between pair h buffers (+4 banks; 16B mult)
#define XPAD  66      // ULL stride between pair x buffers (+4 banks; 16B mult)

__global__ void __launch_bounds__(32, 4)
rnn_fused_kernel(const float* __restrict__ x,
                 const float* __restrict__ W_ih,
                 const float* __restrict__ W_hh,
                 const float* __restrict__ b_ih,
                 const float* __restrict__ b_hh,
                 const float* __restrict__ W_out,
                 const float* __restrict__ b_out,
                 float* __restrict__ out)
{
    // Double-buffered h and x-chunk staging, per pair, interleaved (rowA,rowB)
    __shared__ __align__(16) ULL hb[2][NP][HPAD];
    __shared__ __align__(16) ULL xb[2][NP][XPAD];

    const int lane = threadIdx.x;       // 0..31
    const int llo  = lane & 15;
    const int half = lane >> 4;
    const size_t base = (size_t)blockIdx.x * (2 * NP);  // first of 8 rows

    const float C = 2.885390081777927f; // 2*log2(e), folded into weights

    // ---- weights: W_hh rows llo and llo+16, scaled, duplicated ----
    ULL wA[HH], wB[HH];
    {
        const float4* ra = (const float4*)(W_hh + llo * HH);
        const float4* rb = (const float4*)(W_hh + (llo + 16) * HH);
        #pragma unroll
        for (int k = 0; k < HH / 4; ++k) {
            float4 va = ra[k], vb = rb[k];
            wA[4*k+0] = dup2(C*va.x); wA[4*k+1] = dup2(C*va.y);
            wA[4*k+2] = dup2(C*va.z); wA[4*k+3] = dup2(C*va.w);
            wB[4*k+0] = dup2(C*vb.x); wB[4*k+1] = dup2(C*vb.y);
            wB[4*k+2] = dup2(C*vb.z); wB[4*k+3] = dup2(C*vb.w);
        }
    }
    ULL wihA[FF], wihB[FF];
    {
        const float4* ra = (const float4*)(W_ih + llo * FF);
        const float4* rb = (const float4*)(W_ih + (llo + 16) * FF);
        #pragma unroll
        for (int k = 0; k < FF / 4; ++k) {
            float4 va = ra[k], vb = rb[k];
            wihA[4*k+0] = dup2(C*va.x); wihA[4*k+1] = dup2(C*va.y);
            wihA[4*k+2] = dup2(C*va.z); wihA[4*k+3] = dup2(C*va.w);
            wihB[4*k+0] = dup2(C*vb.x); wihB[4*k+1] = dup2(C*vb.y);
            wihB[4*k+2] = dup2(C*vb.z); wihB[4*k+3] = dup2(C*vb.w);
        }
    }
    const ULL biasA = dup2(C * (b_ih[llo]      + b_hh[llo]));
    const ULL biasB = dup2(C * (b_ih[llo + 16] + b_hh[llo + 16]));

    // h0 = 0 for all 4 pairs (each half initializes its pair in both groups)
    hb[0][half][llo]          = 0ULL;
    hb[0][half][llo + 16]     = 0ULL;
    hb[0][2 + half][llo]      = 0ULL;
    hb[0][2 + half][llo + 16] = 0ULL;

    // ---- x chunk prefetch: 8 rows x 16 float4 = 128 float4, 4 per lane ----
    float4 pre[4];
    #pragma unroll
    for (int k = 0; k < 4; ++k) {
        const int i = lane + 32 * k;
        pre[k] = *(const float4*)(x + (base + (i >> 4)) * (size_t)(TT * FF)
                                    + (i & 15) * 4);
    }

    const int NCHUNK = TT / CHUNK;   // 256
    for (int c = 0; c < NCHUNK; ++c) {
        // stage prefetched chunk: interleaved (rowEven, rowOdd) per pair
        {
            const int buf = c & 1;
            #pragma unroll
            for (int k = 0; k < 4; ++k) {
                const int i    = lane + 32 * k;
                const int row  = i >> 4;
                const int pos  = i & 15;
                const int pair = row >> 1;
                const int slot = row & 1;
                float* xs = (float*)&xb[buf][pair][0];
                const float4 v = pre[k];
                xs[(pos*4 + 0) * 2 + slot] = v.x;
                xs[(pos*4 + 1) * 2 + slot] = v.y;
                xs[(pos*4 + 2) * 2 + slot] = v.z;
                xs[(pos*4 + 3) * 2 + slot] = v.w;
            }
        }
        if (c + 1 < NCHUNK) {
            #pragma unroll
            for (int k = 0; k < 4; ++k) {
                const int i = lane + 32 * k;
                pre[k] = *(const float4*)(x + (base + (i >> 4)) * (size_t)(TT * FF)
                                            + (size_t)(c + 1) * (CHUNK * FF)
                                            + (i & 15) * 4);
            }
        }
        __syncwarp();

        #pragma unroll
        for (int s = 0; s < CHUNK; ++s) {
            const int t = c * CHUNK + s;
            const ULL* hr0 = &hb[t & 1][half][0];
            const ULL* hr1 = &hb[t & 1][2 + half][0];
            const ULL* xr0 = &xb[c & 1][half][s * FF];
            const ULL* xr1 = &xb[c & 1][2 + half][s * FF];

            // ---- group 0: xp + recurrent ----
            ULL a0 = biasA, a1 = 0ULL, c0 = biasB, c1 = 0ULL;
            #pragma unroll
            for (int f = 0; f < FF; f += 2) {
                ulonglong2 xv = *(const ulonglong2*)&xr0[f];
                a0 = ffma2(xv.x, wihA[f],     a0);
                a1 = ffma2(xv.y, wihA[f + 1], a1);
                c0 = ffma2(xv.x, wihB[f],     c0);
                c1 = ffma2(xv.y, wihB[f + 1], c1);
            }
            #pragma unroll
            for (int j = 0; j < HH; j += 2) {
                ulonglong2 hv = *(const ulonglong2*)&hr0[j];
                a0 = ffma2(hv.x, wA[j],     a0);
                a1 = ffma2(hv.y, wA[j + 1], a1);
                c0 = ffma2(hv.x, wB[j],     c0);
                c1 = ffma2(hv.y, wB[j + 1], c1);
            }

            // ---- group 1: xp + recurrent (independent of group 0) ----
            ULL d0 = biasA, d1 = 0ULL, e0 = biasB, e1 = 0ULL;
            #pragma unroll
            for (int f = 0; f < FF; f += 2) {
                ulonglong2 xv = *(const ulonglong2*)&xr1[f];
                d0 = ffma2(xv.x, wihA[f],     d0);
                d1 = ffma2(xv.y, wihA[f + 1], d1);
                e0 = ffma2(xv.x, wihB[f],     e0);
                e1 = ffma2(xv.y, wihB[f + 1], e1);
            }
            #pragma unroll
            for (int j = 0; j < HH; j += 2) {
                ulonglong2 hv = *(const ulonglong2*)&hr1[j];
                d0 = ffma2(hv.x, wA[j],     d0);
                d1 = ffma2(hv.y, wA[j + 1], d1);
                e0 = ffma2(hv.x, wB[j],     e0);
                e1 = ffma2(hv.y, wB[j + 1], e1);
            }

            ULL* hw = &hb[(t + 1) & 1][0][0];

            // ---- group 0 tail (MUFU) overlaps group 1's FMA issue ----
            {
                const ULL accA = fadd2(a0, a1);
                const ULL accB = fadd2(c0, c1);
                float u0, u1, u2, u3;
                unpack2(accA, u0, u1);
                unpack2(accB, u2, u3);
                const float r0 = tanh_from_scaled(u0);
                const float r1 = tanh_from_scaled(u1);
                const float r2 = tanh_from_scaled(u2);
                const float r3 = tanh_from_scaled(u3);
                ULL* h0 = hw + half * HPAD;
                h0[llo]      = pack2(r0, r1);
                h0[llo + 16] = pack2(r2, r3);
            }
            // ---- group 1 tail ----
            {
                const ULL accA = fadd2(d0, d1);
                const ULL accB = fadd2(e0, e1);
                float u0, u1, u2, u3;
                unpack2(accA, u0, u1);
                unpack2(accB, u2, u3);
                const float r0 = tanh_from_scaled(u0);
                const float r1 = tanh_from_scaled(u1);
                const float r2 = tanh_from_scaled(u2);
                const float r3 = tanh_from_scaled(u3);
                ULL* h1 = hw + (2 + half) * HPAD;
                h1[llo]      = pack2(r0, r1);
                h1[llo + 16] = pack2(r2, r3);
            }
            __syncwarp();
        }
    }

    // ---- output head: y = h_final @ W_out^T + b_out ----
    // T=2048 even -> final h in buffer 0; last __syncwarp already done.
    if (llo < OO) {
        #pragma unroll
        for (int g = 0; g < 2; ++g) {
            const ULL* hf = &hb[0][2 * g + half][0];
            float ya = b_out[llo];
            float yb = ya;
            #pragma unroll
            for (int j = 0; j < HH; ++j) {
                float ha, hc;
                unpack2(hf[j], ha, hc);
                const float wv = W_out[llo * HH + j];
                ya = fmaf(wv, ha, ya);
                yb = fmaf(wv, hc, yb);
            }
            const size_t r0 = base + 2 * (2 * g + half);
            out[r0 * OO + llo]       = ya;
            out[(r0 + 1) * OO + llo] = yb;
        }
    }
}

extern "C" void kernel_launch(void* const* d_in, const int* in_sizes, int n_in,
                              void* d_out, int out_size)
{
    const float* x     = (const float*)d_in[0];
    const float* W_ih  = (const float*)d_in[1];
    const float* W_hh  = (const float*)d_in[2];
    const float* b_ih  = (const float*)d_in[3];
    const float* b_hh  = (const float*)d_in[4];
    const float* W_out = (const float*)d_in[5];
    const float* b_out = (const float*)d_in[6];
    float* out = (float*)d_out;

    // 4096 rows / 8 per warp = 512 one-warp blocks (~1 warp per SMSP;
    // latency hiding is intra-warp via the two groups)
    rnn_fused_kernel<<<512, 32>>>(x, W_ih, W_hh, b_ih, b_hh, W_out, b_out, out);
}

// round 9
// speedup vs baseline: 1.5434x; 1.5434x over previous
#include <cuda_runtime.h>
#include <cuda_bf16.h>

typedef unsigned long long ULL;

// ---------------- f32x2 packed helpers (sm_100+) ----------------
__device__ __forceinline__ ULL ffma2(ULL a, ULL b, ULL c) {
    ULL d;
    asm("fma.rn.f32x2 %0, %1, %2, %3;" : "=l"(d) : "l"(a), "l"(b), "l"(c));
    return d;
}
__device__ __forceinline__ ULL fadd2(ULL a, ULL b) {
    ULL d;
    asm("add.rn.f32x2 %0, %1, %2;" : "=l"(d) : "l"(a), "l"(b));
    return d;
}
__device__ __forceinline__ ULL dup2(float w) {
    unsigned u = __float_as_uint(w);
    ULL d;
    asm("mov.b64 %0, {%1, %1};" : "=l"(d) : "r"(u));
    return d;
}
__device__ __forceinline__ ULL pack2(float lo, float hi) {
    ULL d;
    unsigned a = __float_as_uint(lo), b = __float_as_uint(hi);
    asm("mov.b64 %0, {%1, %2};" : "=l"(d) : "r"(a), "r"(b));
    return d;
}
__device__ __forceinline__ void unpack2(ULL v, float& lo, float& hi) {
    unsigned a, b;
    asm("mov.b64 {%0, %1}, %2;" : "=r"(a), "=r"(b) : "l"(v));
    lo = __uint_as_float(a);
    hi = __uint_as_float(b);
}

// Single-op MUFU tanh (sm_75+). Per-step abs err <= ~5e-4; R5 measured ~5x
// contraction damping of per-step error, so final rel err ~1e-4 << 1e-3 gate.
__device__ __forceinline__ float tanh_fast(float x) {
    float r;
    asm("tanh.approx.f32 %0, %1;" : "=f"(r) : "f"(x));
    return r;
}

// ---------------- config ----------------
// B=4096, T=2048, F=8, H=32, O=8
// R5 mapping (best: 655us): one 32-thread block = one warp = 4 batch rows
// (2 f32x2 pairs). Lanes 0-15 own pair 0, lanes 16-31 pair 1; each lane
// computes h rows llo and llo+16 (those W_hh rows dup'd in registers), so
// one LDS.128 of h serves both half-warps. 1024 one-warp blocks, all
// resident (<=7/SM).
// R8 changes vs R5 (serial-chain surgery; step chain ~350 -> ~210 cyc):
//  - xp software pipeline: xp_{t+1} computed during step t (off the
//    post-sync critical path); x chunks staged one ahead.
//  - tanh.approx.f32 replaces the ex2+rcp sequence (40-cyc chain -> 16).
#define TT    2048
#define FF    8
#define HH    32
#define OO    8
#define CHUNK 8       // timesteps of x staged per SMEM refill
#define HPAD  34      // ULL stride between pair h buffers (+4 banks; 16B mult)
#define XPAD  66      // ULL stride between pair x buffers (+4 banks; 16B mult)

__global__ void __launch_bounds__(32, 7)
rnn_fused_kernel(const float* __restrict__ x,
                 const float* __restrict__ W_ih,
                 const float* __restrict__ W_hh,
                 const float* __restrict__ b_ih,
                 const float* __restrict__ b_hh,
                 const float* __restrict__ W_out,
                 const float* __restrict__ b_out,
                 float* __restrict__ out)
{
    // Double-buffered h and x-chunk staging, per pair, interleaved (rowA,rowB)
    __shared__ __align__(16) ULL hb[2][2][HPAD];
    __shared__ __align__(16) ULL xb[2][2][XPAD];

    const int lane = threadIdx.x;       // 0..31
    const int llo  = lane & 15;
    const int half = lane >> 4;
    const size_t base = (size_t)blockIdx.x * 4;  // first of 4 batch rows

    // ---- weights (UNSCALED): W_hh rows llo and llo+16, duplicated ----
    ULL wA[HH], wB[HH];
    {
        const float4* ra = (const float4*)(W_hh + llo * HH);
        const float4* rb = (const float4*)(W_hh + (llo + 16) * HH);
        #pragma unroll
        for (int k = 0; k < HH / 4; ++k) {
            float4 va = ra[k], vb = rb[k];
            wA[4*k+0] = dup2(va.x); wA[4*k+1] = dup2(va.y);
            wA[4*k+2] = dup2(va.z); wA[4*k+3] = dup2(va.w);
            wB[4*k+0] = dup2(vb.x); wB[4*k+1] = dup2(vb.y);
            wB[4*k+2] = dup2(vb.z); wB[4*k+3] = dup2(vb.w);
        }
    }
    ULL wihA[FF], wihB[FF];
    {
        const float4* ra = (const float4*)(W_ih + llo * FF);
        const float4* rb = (const float4*)(W_ih + (llo + 16) * FF);
        #pragma unroll
        for (int k = 0; k < FF / 4; ++k) {
            float4 va = ra[k], vb = rb[k];
            wihA[4*k+0] = dup2(va.x); wihA[4*k+1] = dup2(va.y);
            wihA[4*k+2] = dup2(va.z); wihA[4*k+3] = dup2(va.w);
            wihB[4*k+0] = dup2(vb.x); wihB[4*k+1] = dup2(vb.y);
            wihB[4*k+2] = dup2(vb.z); wihB[4*k+3] = dup2(vb.w);
        }
    }
    const ULL biasA = dup2(b_ih[llo]      + b_hh[llo]);
    const ULL biasB = dup2(b_ih[llo + 16] + b_hh[llo + 16]);

    // h0 = 0 for both pairs
    hb[0][half][llo]      = 0ULL;
    hb[0][half][llo + 16] = 0ULL;

    const int NCHUNK = TT / CHUNK;   // 256

    // ---- helpers for x prefetch/staging (4 rows x 16 float4 per chunk) ----
    // lane covers float4 i = lane and i = lane+32: row = i>>4, pos = i&15.
    float4 pre0, pre1;
    {   // load chunk 0
        const int i0 = lane, i1 = lane + 32;
        pre0 = *(const float4*)(x + (base + (i0 >> 4)) * (size_t)(TT * FF) + (i0 & 15) * 4);
        pre1 = *(const float4*)(x + (base + (i1 >> 4)) * (size_t)(TT * FF) + (i1 & 15) * 4);
    }
    // stage chunk 0 into buffer 0 (interleaved (rowEven,rowOdd) per pair)
    {
        #pragma unroll
        for (int k = 0; k < 2; ++k) {
            const int i    = lane + 32 * k;
            const int row  = i >> 4;
            const int pos  = i & 15;
            const int pair = row >> 1;
            const int slot = row & 1;
            float* xs = (float*)&xb[0][pair][0];
            const float4 v = (k == 0) ? pre0 : pre1;
            xs[(pos*4 + 0) * 2 + slot] = v.x;
            xs[(pos*4 + 1) * 2 + slot] = v.y;
            xs[(pos*4 + 2) * 2 + slot] = v.z;
            xs[(pos*4 + 3) * 2 + slot] = v.w;
        }
    }
    __syncwarp();

    // initial xp for t=0 (bias included)
    ULL xpA, xpB;
    {
        const ULL* xr = &xb[0][half][0];
        ULL p0 = biasA, p1 = 0ULL, q0 = biasB, q1 = 0ULL;
        #pragma unroll
        for (int f = 0; f < FF; f += 2) {
            ulonglong2 xv = *(const ulonglong2*)&xr[f];
            p0 = ffma2(xv.x, wihA[f],     p0);
            p1 = ffma2(xv.y, wihA[f + 1], p1);
            q0 = ffma2(xv.x, wihB[f],     q0);
            q1 = ffma2(xv.y, wihB[f + 1], q1);
        }
        xpA = fadd2(p0, p1);
        xpB = fadd2(q0, q1);
    }

    // prefetch chunk 1
    {
        const int i0 = lane, i1 = lane + 32;
        pre0 = *(const float4*)(x + (base + (i0 >> 4)) * (size_t)(TT * FF)
                                  + (size_t)(CHUNK * FF) + (i0 & 15) * 4);
        pre1 = *(const float4*)(x + (base + (i1 >> 4)) * (size_t)(TT * FF)
                                  + (size_t)(CHUNK * FF) + (i1 & 15) * 4);
    }

    for (int c = 0; c < NCHUNK; ++c) {
        // stage chunk c+1 into buffer (c+1)&1 (needed by step s=7's xp-next)
        if (c + 1 < NCHUNK) {
            const int buf = (c + 1) & 1;
            #pragma unroll
            for (int k = 0; k < 2; ++k) {
                const int i    = lane + 32 * k;
                const int row  = i >> 4;
                const int pos  = i & 15;
                const int pair = row >> 1;
                const int slot = row & 1;
                float* xs = (float*)&xb[buf][pair][0];
                const float4 v = (k == 0) ? pre0 : pre1;
                xs[(pos*4 + 0) * 2 + slot] = v.x;
                xs[(pos*4 + 1) * 2 + slot] = v.y;
                xs[(pos*4 + 2) * 2 + slot] = v.z;
                xs[(pos*4 + 3) * 2 + slot] = v.w;
            }
        }
        if (c + 2 < NCHUNK) {
            const int i0 = lane, i1 = lane + 32;
            pre0 = *(const float4*)(x + (base + (i0 >> 4)) * (size_t)(TT * FF)
                                      + (size_t)(c + 2) * (CHUNK * FF) + (i0 & 15) * 4);
            pre1 = *(const float4*)(x + (base + (i1 >> 4)) * (size_t)(TT * FF)
                                      + (size_t)(c + 2) * (CHUNK * FF) + (i1 & 15) * 4);
        }
        __syncwarp();

        #pragma unroll
        for (int s = 0; s < CHUNK; ++s) {
            const int t = c * CHUNK + s;
            const ULL* hr = &hb[t & 1][half][0];

            // ---- recurrent matvec, starting from pipelined xp ----
            ULL a0 = xpA, a1 = 0ULL;
            ULL c0 = xpB, c1 = 0ULL;
            #pragma unroll
            for (int j = 0; j < HH; j += 2) {
                ulonglong2 hv = *(const ulonglong2*)&hr[j];
                a0 = ffma2(hv.x, wA[j],     a0);
                a1 = ffma2(hv.y, wA[j + 1], a1);
                c0 = ffma2(hv.x, wB[j],     c0);
                c1 = ffma2(hv.y, wB[j + 1], c1);
            }

            // ---- xp for t+1 (h-independent; fills the FMA/MUFU shadow).
            // s<7: current buffer, slot s+1. s==7: next chunk's buffer, slot 0
            // (staged at this chunk's top). Last step reads stale data; unused.
            {
                const ULL* xn = (s < CHUNK - 1) ? &xb[c & 1][half][(s + 1) * FF]
                                                : &xb[(c + 1) & 1][half][0];
                ULL p0 = biasA, p1 = 0ULL, q0 = biasB, q1 = 0ULL;
                #pragma unroll
                for (int f = 0; f < FF; f += 2) {
                    ulonglong2 xv = *(const ulonglong2*)&xn[f];
                    p0 = ffma2(xv.x, wihA[f],     p0);
                    p1 = ffma2(xv.y, wihA[f + 1], p1);
                    q0 = ffma2(xv.x, wihB[f],     q0);
                    q1 = ffma2(xv.y, wihB[f + 1], q1);
                }
                xpA = fadd2(p0, p1);
                xpB = fadd2(q0, q1);
            }

            const ULL accA = fadd2(a0, a1);
            const ULL accB = fadd2(c0, c1);

            float u0, u1, u2, u3;
            unpack2(accA, u0, u1);
            unpack2(accB, u2, u3);
            const float r0 = tanh_fast(u0);
            const float r1 = tanh_fast(u1);
            const float r2 = tanh_fast(u2);
            const float r3 = tanh_fast(u3);

            ULL* hw = &hb[(t + 1) & 1][half][0];
            hw[llo]      = pack2(r0, r1);
            hw[llo + 16] = pack2(r2, r3);
            __syncwarp();
        }
    }

    // ---- output head: y = h_final @ W_out^T + b_out ----
    // T=2048 even -> final h in buffer 0; last __syncwarp already done.
    if (llo < OO) {
        const ULL* hf = &hb[0][half][0];
        float ya = b_out[llo];
        float yb = ya;
        #pragma unroll
        for (int j = 0; j < HH; ++j) {
            float ha, hc;
            unpack2(hf[j], ha, hc);
            const float wv = W_out[llo * HH + j];
            ya = fmaf(wv, ha, ya);
            yb = fmaf(wv, hc, yb);
        }
        const size_t r0 = base + 2 * half;
        out[r0 * OO + llo]       = ya;
        out[(r0 + 1) * OO + llo] = yb;
    }
}

extern "C" void kernel_launch(void* const* d_in, const int* in_sizes, int n_in,
                              void* d_out, int out_size)
{
    const float* x     = (const float*)d_in[0];
    const float* W_ih  = (const float*)d_in[1];
    const float* W_hh  = (const float*)d_in[2];
    const float* b_ih  = (const float*)d_in[3];
    const float* b_hh  = (const float*)d_in[4];
    const float* W_out = (const float*)d_in[5];
    const float* b_out = (const float*)d_in[6];
    float* out = (float*)d_out;

    // 4096 rows / 4 per warp = 1024 one-warp blocks (all resident, <=7/SM)
    rnn_fused_kernel<<<1024, 32>>>(x, W_ih, W_hh, b_ih, b_hh, W_out, b_out, out);
}

// round 10
// speedup vs baseline: 1.5591x; 1.0102x over previous
#include <cuda_runtime.h>
#include <cuda_bf16.h>

typedef unsigned long long ULL;

// ---------------- f32x2 packed helpers (sm_100+) ----------------
__device__ __forceinline__ ULL ffma2(ULL a, ULL b, ULL c) {
    ULL d;
    asm("fma.rn.f32x2 %0, %1, %2, %3;" : "=l"(d) : "l"(a), "l"(b), "l"(c));
    return d;
}
__device__ __forceinline__ ULL fadd2(ULL a, ULL b) {
    ULL d;
    asm("add.rn.f32x2 %0, %1, %2;" : "=l"(d) : "l"(a), "l"(b));
    return d;
}
__device__ __forceinline__ ULL dup2(float w) {
    unsigned u = __float_as_uint(w);
    ULL d;
    asm("mov.b64 %0, {%1, %1};" : "=l"(d) : "r"(u));
    return d;
}
__device__ __forceinline__ ULL pack2(float lo, float hi) {
    ULL d;
    unsigned a = __float_as_uint(lo), b = __float_as_uint(hi);
    asm("mov.b64 %0, {%1, %2};" : "=l"(d) : "r"(a), "r"(b));
    return d;
}
__device__ __forceinline__ void unpack2(ULL v, float& lo, float& hi) {
    unsigned a, b;
    asm("mov.b64 {%0, %1}, %2;" : "=r"(a), "=r"(b) : "l"(v));
    lo = __uint_as_float(a);
    hi = __uint_as_float(b);
}

// Single-op MUFU tanh (sm_75+). R9 measured final rel_err 3.6e-6.
__device__ __forceinline__ float tanh_fast(float x) {
    float r;
    asm("tanh.approx.f32 %0, %1;" : "=f"(r) : "f"(x));
    return r;
}

// ---------------- config ----------------
// B=4096, T=2048, F=8, H=32, O=8
// Mapping (best lineage, R5/R8): one 32-thread block = one warp = 4 batch
// rows (2 f32x2 pairs). Lanes 0-15 own pair 0, lanes 16-31 pair 1; each
// lane computes h rows llo and llo+16 (those W_hh rows dup'd in regs), so
// one LDS.128 of h serves both half-warps. 1024 one-warp blocks.
// R10 vs R8 (serial chain S ~260 -> ~205; wall = 2S on 2-warp SMSPs):
//  - per-step __syncwarp removed: h exchange is intra-half-warp, straight-
//    line code (one PC) -> same-warp in-order STS->LDS suffices. The only
//    cross-half traffic (x staging) keeps its chunk-boundary __syncwarp.
//  - tail reorder: fadds -> tanh issue -> xp block (fills tanh latency)
//    -> STS, instead of xp before the tail.
#define TT    2048
#define FF    8
#define HH    32
#define OO    8
#define CHUNK 8       // timesteps of x staged per SMEM refill
#define HPAD  34      // ULL stride between pair h buffers (+4 banks; 16B mult)
#define XPAD  66      // ULL stride between pair x buffers (+4 banks; 16B mult)

__global__ void __launch_bounds__(32, 7)
rnn_fused_kernel(const float* __restrict__ x,
                 const float* __restrict__ W_ih,
                 const float* __restrict__ W_hh,
                 const float* __restrict__ b_ih,
                 const float* __restrict__ b_hh,
                 const float* __restrict__ W_out,
                 const float* __restrict__ b_out,
                 float* __restrict__ out)
{
    // Double-buffered h and x-chunk staging, per pair, interleaved (rowA,rowB)
    __shared__ __align__(16) ULL hb[2][2][HPAD];
    __shared__ __align__(16) ULL xb[2][2][XPAD];

    const int lane = threadIdx.x;       // 0..31
    const int llo  = lane & 15;
    const int half = lane >> 4;
    const size_t base = (size_t)blockIdx.x * 4;  // first of 4 batch rows

    // ---- weights: W_hh rows llo and llo+16, duplicated for f32x2 ----
    ULL wA[HH], wB[HH];
    {
        const float4* ra = (const float4*)(W_hh + llo * HH);
        const float4* rb = (const float4*)(W_hh + (llo + 16) * HH);
        #pragma unroll
        for (int k = 0; k < HH / 4; ++k) {
            float4 va = ra[k], vb = rb[k];
            wA[4*k+0] = dup2(va.x); wA[4*k+1] = dup2(va.y);
            wA[4*k+2] = dup2(va.z); wA[4*k+3] = dup2(va.w);
            wB[4*k+0] = dup2(vb.x); wB[4*k+1] = dup2(vb.y);
            wB[4*k+2] = dup2(vb.z); wB[4*k+3] = dup2(vb.w);
        }
    }
    ULL wihA[FF], wihB[FF];
    {
        const float4* ra = (const float4*)(W_ih + llo * FF);
        const float4* rb = (const float4*)(W_ih + (llo + 16) * FF);
        #pragma unroll
        for (int k = 0; k < FF / 4; ++k) {
            float4 va = ra[k], vb = rb[k];
            wihA[4*k+0] = dup2(va.x); wihA[4*k+1] = dup2(va.y);
            wihA[4*k+2] = dup2(va.z); wihA[4*k+3] = dup2(va.w);
            wihB[4*k+0] = dup2(vb.x); wihB[4*k+1] = dup2(vb.y);
            wihB[4*k+2] = dup2(vb.z); wihB[4*k+3] = dup2(vb.w);
        }
    }
    const ULL biasA = dup2(b_ih[llo]      + b_hh[llo]);
    const ULL biasB = dup2(b_ih[llo + 16] + b_hh[llo + 16]);

    // h0 = 0 for both pairs
    hb[0][half][llo]      = 0ULL;
    hb[0][half][llo + 16] = 0ULL;

    const int NCHUNK = TT / CHUNK;   // 256

    // ---- x prefetch/staging: 4 rows x 16 float4 per chunk, 2 per lane ----
    float4 pre0, pre1;
    {   // load chunk 0
        const int i0 = lane, i1 = lane + 32;
        pre0 = *(const float4*)(x + (base + (i0 >> 4)) * (size_t)(TT * FF) + (i0 & 15) * 4);
        pre1 = *(const float4*)(x + (base + (i1 >> 4)) * (size_t)(TT * FF) + (i1 & 15) * 4);
    }
    // stage chunk 0 into buffer 0 (interleaved (rowEven,rowOdd) per pair)
    {
        #pragma unroll
        for (int k = 0; k < 2; ++k) {
            const int i    = lane + 32 * k;
            const int row  = i >> 4;
            const int pos  = i & 15;
            const int pair = row >> 1;
            const int slot = row & 1;
            float* xs = (float*)&xb[0][pair][0];
            const float4 v = (k == 0) ? pre0 : pre1;
            xs[(pos*4 + 0) * 2 + slot] = v.x;
            xs[(pos*4 + 1) * 2 + slot] = v.y;
            xs[(pos*4 + 2) * 2 + slot] = v.z;
            xs[(pos*4 + 3) * 2 + slot] = v.w;
        }
    }
    __syncwarp();

    // initial xp for t=0 (bias included)
    ULL xpA, xpB;
    {
        const ULL* xr = &xb[0][half][0];
        ULL p0 = biasA, p1 = 0ULL, q0 = biasB, q1 = 0ULL;
        #pragma unroll
        for (int f = 0; f < FF; f += 2) {
            ulonglong2 xv = *(const ulonglong2*)&xr[f];
            p0 = ffma2(xv.x, wihA[f],     p0);
            p1 = ffma2(xv.y, wihA[f + 1], p1);
            q0 = ffma2(xv.x, wihB[f],     q0);
            q1 = ffma2(xv.y, wihB[f + 1], q1);
        }
        xpA = fadd2(p0, p1);
        xpB = fadd2(q0, q1);
    }

    // prefetch chunk 1
    {
        const int i0 = lane, i1 = lane + 32;
        pre0 = *(const float4*)(x + (base + (i0 >> 4)) * (size_t)(TT * FF)
                                  + (size_t)(CHUNK * FF) + (i0 & 15) * 4);
        pre1 = *(const float4*)(x + (base + (i1 >> 4)) * (size_t)(TT * FF)
                                  + (size_t)(CHUNK * FF) + (i1 & 15) * 4);
    }

    for (int c = 0; c < NCHUNK; ++c) {
        // stage chunk c+1 into buffer (c+1)&1 (needed by step s=7's xp-next)
        if (c + 1 < NCHUNK) {
            const int buf = (c + 1) & 1;
            #pragma unroll
            for (int k = 0; k < 2; ++k) {
                const int i    = lane + 32 * k;
                const int row  = i >> 4;
                const int pos  = i & 15;
                const int pair = row >> 1;
                const int slot = row & 1;
                float* xs = (float*)&xb[buf][pair][0];
                const float4 v = (k == 0) ? pre0 : pre1;
                xs[(pos*4 + 0) * 2 + slot] = v.x;
                xs[(pos*4 + 1) * 2 + slot] = v.y;
                xs[(pos*4 + 2) * 2 + slot] = v.z;
                xs[(pos*4 + 3) * 2 + slot] = v.w;
            }
        }
        if (c + 2 < NCHUNK) {
            const int i0 = lane, i1 = lane + 32;
            pre0 = *(const float4*)(x + (base + (i0 >> 4)) * (size_t)(TT * FF)
                                      + (size_t)(c + 2) * (CHUNK * FF) + (i0 & 15) * 4);
            pre1 = *(const float4*)(x + (base + (i1 >> 4)) * (size_t)(TT * FF)
                                      + (size_t)(c + 2) * (CHUNK * FF) + (i1 & 15) * 4);
        }
        // guards cross-half-warp x staging (once per CHUNK steps)
        __syncwarp();

        #pragma unroll
        for (int s = 0; s < CHUNK; ++s) {
            const int t = c * CHUNK + s;
            const ULL* hr = &hb[t & 1][half][0];

            // ---- recurrent matvec, starting from pipelined xp ----
            ULL a0 = xpA, a1 = 0ULL;
            ULL c0 = xpB, c1 = 0ULL;
            #pragma unroll
            for (int j = 0; j < HH; j += 2) {
                ulonglong2 hv = *(const ulonglong2*)&hr[j];
                a0 = ffma2(hv.x, wA[j],     a0);
                a1 = ffma2(hv.y, wA[j + 1], a1);
                c0 = ffma2(hv.x, wB[j],     c0);
                c1 = ffma2(hv.y, wB[j + 1], c1);
            }
            const ULL accA = fadd2(a0, a1);
            const ULL accB = fadd2(c0, c1);

            // issue all 4 tanh (MUFU) ...
            float u0, u1, u2, u3;
            unpack2(accA, u0, u1);
            unpack2(accB, u2, u3);
            const float r0 = tanh_fast(u0);
            const float r1 = tanh_fast(u1);
            const float r2 = tanh_fast(u2);
            const float r3 = tanh_fast(u3);

            // ---- xp for t+1 fills the tanh-latency window (h-independent).
            // s<7: current buffer slot s+1; s==7: next chunk's buffer slot 0
            // (staged at this chunk's top). Last global step computes unused.
            {
                const ULL* xn = (s < CHUNK - 1) ? &xb[c & 1][half][(s + 1) * FF]
                                                : &xb[(c + 1) & 1][half][0];
                ULL p0 = biasA, p1 = 0ULL, q0 = biasB, q1 = 0ULL;
                #pragma unroll
                for (int f = 0; f < FF; f += 2) {
                    ulonglong2 xv = *(const ulonglong2*)&xn[f];
                    p0 = ffma2(xv.x, wihA[f],     p0);
                    p1 = ffma2(xv.y, wihA[f + 1], p1);
                    q0 = ffma2(xv.x, wihB[f],     q0);
                    q1 = ffma2(xv.y, wihB[f + 1], q1);
                }
                xpA = fadd2(p0, p1);
                xpB = fadd2(q0, q1);
            }

            // ---- h writeback. NO per-step __syncwarp: producer lanes ==
            // consumer lanes (intra-half-warp), straight-line code, same-warp
            // smem ops are in-order; compiler keeps order (same object hb).
            ULL* hw = &hb[(t + 1) & 1][half][0];
            hw[llo]      = pack2(r0, r1);
            hw[llo + 16] = pack2(r2, r3);
        }
    }

    __syncwarp();

    // ---- output head: y = h_final @ W_out^T + b_out ----
    // T=2048 even -> final h in buffer 0.
    if (llo < OO) {
        const ULL* hf = &hb[0][half][0];
        float ya = b_out[llo];
        float yb = ya;
        #pragma unroll
        for (int j = 0; j < HH; ++j) {
            float ha, hc;
            unpack2(hf[j], ha, hc);
            const float wv = W_out[llo * HH + j];
            ya = fmaf(wv, ha, ya);
            yb = fmaf(wv, hc, yb);
        }
        const size_t r0 = base + 2 * half;
        out[r0 * OO + llo]       = ya;
        out[(r0 + 1) * OO + llo] = yb;
    }
}

extern "C" void kernel_launch(void* const* d_in, const int* in_sizes, int n_in,
                              void* d_out, int out_size)
{
    const float* x     = (const float*)d_in[0];
    const float* W_ih  = (const float*)d_in[1];
    const float* W_hh  = (const float*)d_in[2];
    const float* b_ih  = (const float*)d_in[3];
    const float* b_hh  = (const float*)d_in[4];
    const float* W_out = (const float*)d_in[5];
    const float* b_out = (const float*)d_in[6];
    float* out = (float*)d_out;

    // 4096 rows / 4 per warp = 1024 one-warp blocks (all resident, <=7/SM)
    rnn_fused_kernel<<<1024, 32>>>(x, W_ih, W_hh, b_ih, b_hh, W_out, b_out, out);
}

// round 12
// speedup vs baseline: 1.6330x; 1.0474x over previous
#include <cuda_runtime.h>
#include <cuda_bf16.h>

typedef unsigned long long ULL;

// ---------------- f32x2 packed helpers (sm_100+) ----------------
__device__ __forceinline__ ULL ffma2(ULL a, ULL b, ULL c) {
    ULL d;
    asm("fma.rn.f32x2 %0, %1, %2, %3;" : "=l"(d) : "l"(a), "l"(b), "l"(c));
    return d;
}
__device__ __forceinline__ ULL fadd2(ULL a, ULL b) {
    ULL d;
    asm("add.rn.f32x2 %0, %1, %2;" : "=l"(d) : "l"(a), "l"(b));
    return d;
}
__device__ __forceinline__ ULL dup2(float w) {
    unsigned u = __float_as_uint(w);
    ULL d;
    asm("mov.b64 %0, {%1, %1};" : "=l"(d) : "r"(u));
    return d;
}
__device__ __forceinline__ ULL pack2(float lo, float hi) {
    ULL d;
    unsigned a = __float_as_uint(lo), b = __float_as_uint(hi);
    asm("mov.b64 %0, {%1, %2};" : "=l"(d) : "r"(a), "r"(b));
    return d;
}
__device__ __forceinline__ void unpack2(ULL v, float& lo, float& hi) {
    unsigned a, b;
    asm("mov.b64 {%0, %1}, %2;" : "=r"(a), "=r"(b) : "l"(v));
    lo = __uint_as_float(a);
    hi = __uint_as_float(b);
}

// Single-op MUFU tanh (sm_75+). Measured final rel_err 3.6e-6.
__device__ __forceinline__ float tanh_fast(float x) {
    float r;
    asm("tanh.approx.f32 %0, %1;" : "=f"(r) : "f"(x));
    return r;
}

// ---------------- config ----------------
// B=4096, T=2048, F=8, H=32, O=8
// R11: engineered ANTIPHASE. R10 diagnosis: wall 517 cyc/step = FMA floor
// 320 (2 warps x 80 FFMA2 x rt2) + ~197 cyc of latency that both
// co-resident warps expose SIMULTANEOUSLY (phase-locked: identical work,
// same start, phase difference is conserved).
// Fix: one 256-thread block per SM (8 warps); warps w and w+4 share an
// SMSP (wid%4). Warps 4-7 run a ~190-cycle dependent-FMA skew chain at
// start -> each SMSP's pair is antiphased; each warp's stall window is
// covered by its partner's FMA-issue block. Phase offset is conserved
// because per-step work is identical and warps never sync in the loop.
// 128 blocks x 8 warps x 4 rows = 4096 rows; 1 block/SM (reg-limited),
// uniform 2 warps/SMSP.
// Everything inside a warp is the proven R10 step (best lineage).
#define TT    2048
#define FF    8
#define HH    32
#define OO    8
#define CHUNK 8       // timesteps of x staged per SMEM refill
#define NW    8       // warps per block
#define HPAD  34      // ULL stride between pair h buffers (+4 banks; 16B mult)
#define XPAD  66      // ULL stride between pair x buffers (+4 banks; 16B mult)

__global__ void __launch_bounds__(32 * NW, 1)
rnn_fused_kernel(const float* __restrict__ x,
                 const float* __restrict__ W_ih,
                 const float* __restrict__ W_hh,
                 const float* __restrict__ b_ih,
                 const float* __restrict__ b_hh,
                 const float* __restrict__ W_out,
                 const float* __restrict__ b_out,
                 float* __restrict__ out)
{
    // Per-warp double-buffered h and x staging (each warp touches only its
    // own [wip] slice; no cross-warp traffic, no __syncthreads in the loop).
    __shared__ __align__(16) ULL hb[NW][2][2][HPAD];
    __shared__ __align__(16) ULL xb[NW][2][2][XPAD];

    const int tid  = threadIdx.x;
    const int wip  = tid >> 5;          // 0..7
    const int lane = tid & 31;
    const int llo  = lane & 15;
    const int half = lane >> 4;
    const size_t base = (size_t)blockIdx.x * (4 * NW) + (size_t)wip * 4;

    // ---- ANTIPHASE SKEW: warps 4-7 (the wid%4 partners of warps 0-3)
    // burn ~190 cycles in a dependent FMA chain before starting. ----
    if (wip >= 4) {
        float z = 1.0f;
        #pragma unroll
        for (int i = 0; i < 48; ++i)
            asm volatile("fma.rn.f32 %0, %0, %1, %2;"
                         : "+f"(z) : "f"(1.0f), "f"(0.0f));
    }

    // ---- weights: W_hh rows llo and llo+16, duplicated for f32x2 ----
    ULL wA[HH], wB[HH];
    {
        const float4* ra = (const float4*)(W_hh + llo * HH);
        const float4* rb = (const float4*)(W_hh + (llo + 16) * HH);
        #pragma unroll
        for (int k = 0; k < HH / 4; ++k) {
            float4 va = ra[k], vb = rb[k];
            wA[4*k+0] = dup2(va.x); wA[4*k+1] = dup2(va.y);
            wA[4*k+2] = dup2(va.z); wA[4*k+3] = dup2(va.w);
            wB[4*k+0] = dup2(vb.x); wB[4*k+1] = dup2(vb.y);
            wB[4*k+2] = dup2(vb.z); wB[4*k+3] = dup2(vb.w);
        }
    }
    ULL wihA[FF], wihB[FF];
    {
        const float4* ra = (const float4*)(W_ih + llo * FF);
        const float4* rb = (const float4*)(W_ih + (llo + 16) * FF);
        #pragma unroll
        for (int k = 0; k < FF / 4; ++k) {
            float4 va = ra[k], vb = rb[k];
            wihA[4*k+0] = dup2(va.x); wihA[4*k+1] = dup2(va.y);
            wihA[4*k+2] = dup2(va.z); wihA[4*k+3] = dup2(va.w);
            wihB[4*k+0] = dup2(vb.x); wihB[4*k+1] = dup2(vb.y);
            wihB[4*k+2] = dup2(vb.z); wihB[4*k+3] = dup2(vb.w);
        }
    }
    const ULL biasA = dup2(b_ih[llo]      + b_hh[llo]);
    const ULL biasB = dup2(b_ih[llo + 16] + b_hh[llo + 16]);

    // h0 = 0 for both pairs
    hb[wip][0][half][llo]      = 0ULL;
    hb[wip][0][half][llo + 16] = 0ULL;

    const int NCHUNK = TT / CHUNK;   // 256

    // ---- x prefetch/staging: 4 rows x 16 float4 per chunk, 2 per lane ----
    float4 pre0, pre1;
    {   // load chunk 0
        const int i0 = lane, i1 = lane + 32;
        pre0 = *(const float4*)(x + (base + (i0 >> 4)) * (size_t)(TT * FF) + (i0 & 15) * 4);
        pre1 = *(const float4*)(x + (base + (i1 >> 4)) * (size_t)(TT * FF) + (i1 & 15) * 4);
    }
    // stage chunk 0 into buffer 0 (interleaved (rowEven,rowOdd) per pair)
    {
        #pragma unroll
        for (int k = 0; k < 2; ++k) {
            const int i    = lane + 32 * k;
            const int row  = i >> 4;
            const int pos  = i & 15;
            const int pair = row >> 1;
            const int slot = row & 1;
            float* xs = (float*)&xb[wip][0][pair][0];
            const float4 v = (k == 0) ? pre0 : pre1;
            xs[(pos*4 + 0) * 2 + slot] = v.x;
            xs[(pos*4 + 1) * 2 + slot] = v.y;
            xs[(pos*4 + 2) * 2 + slot] = v.z;
            xs[(pos*4 + 3) * 2 + slot] = v.w;
        }
    }
    __syncwarp();

    // initial xp for t=0 (bias included)
    ULL xpA, xpB;
    {
        const ULL* xr = &xb[wip][0][half][0];
        ULL p0 = biasA, p1 = 0ULL, q0 = biasB, q1 = 0ULL;
        #pragma unroll
        for (int f = 0; f < FF; f += 2) {
            ulonglong2 xv = *(const ulonglong2*)&xr[f];
            p0 = ffma2(xv.x, wihA[f],     p0);
            p1 = ffma2(xv.y, wihA[f + 1], p1);
            q0 = ffma2(xv.x, wihB[f],     q0);
            q1 = ffma2(xv.y, wihB[f + 1], q1);
        }
        xpA = fadd2(p0, p1);
        xpB = fadd2(q0, q1);
    }

    // prefetch chunk 1
    {
        const int i0 = lane, i1 = lane + 32;
        pre0 = *(const float4*)(x + (base + (i0 >> 4)) * (size_t)(TT * FF)
                                  + (size_t)(CHUNK * FF) + (i0 & 15) * 4);
        pre1 = *(const float4*)(x + (base + (i1 >> 4)) * (size_t)(TT * FF)
                                  + (size_t)(CHUNK * FF) + (i1 & 15) * 4);
    }

    for (int c = 0; c < NCHUNK; ++c) {
        // stage chunk c+1 into buffer (c+1)&1 (needed by step s=7's xp-next)
        if (c + 1 < NCHUNK) {
            const int buf = (c + 1) & 1;
            #pragma unroll
            for (int k = 0; k < 2; ++k) {
                const int i    = lane + 32 * k;
                const int row  = i >> 4;
                const int pos  = i & 15;
                const int pair = row >> 1;
                const int slot = row & 1;
                float* xs = (float*)&xb[wip][buf][pair][0];
                const float4 v = (k == 0) ? pre0 : pre1;
                xs[(pos*4 + 0) * 2 + slot] = v.x;
                xs[(pos*4 + 1) * 2 + slot] = v.y;
                xs[(pos*4 + 2) * 2 + slot] = v.z;
                xs[(pos*4 + 3) * 2 + slot] = v.w;
            }
        }
        if (c + 2 < NCHUNK) {
            const int i0 = lane, i1 = lane + 32;
            pre0 = *(const float4*)(x + (base + (i0 >> 4)) * (size_t)(TT * FF)
                                      + (size_t)(c + 2) * (CHUNK * FF) + (i0 & 15) * 4);
            pre1 = *(const float4*)(x + (base + (i1 >> 4)) * (size_t)(TT * FF)
                                      + (size_t)(c + 2) * (CHUNK * FF) + (i1 & 15) * 4);
        }
        // guards cross-half-warp x staging (once per CHUNK steps)
        __syncwarp();

        #pragma unroll
        for (int s = 0; s < CHUNK; ++s) {
            const int t = c * CHUNK + s;
            const ULL* hr = &hb[wip][t & 1][half][0];

            // ---- recurrent matvec, starting from pipelined xp ----
            ULL a0 = xpA, a1 = 0ULL;
            ULL c0 = xpB, c1 = 0ULL;
            #pragma unroll
            for (int j = 0; j < HH; j += 2) {
                ulonglong2 hv = *(const ulonglong2*)&hr[j];
                a0 = ffma2(hv.x, wA[j],     a0);
                a1 = ffma2(hv.y, wA[j + 1], a1);
                c0 = ffma2(hv.x, wB[j],     c0);
                c1 = ffma2(hv.y, wB[j + 1], c1);
            }
            const ULL accA = fadd2(a0, a1);
            const ULL accB = fadd2(c0, c1);

            // issue all 4 tanh (MUFU) ...
            float u0, u1, u2, u3;
            unpack2(accA, u0, u1);
            unpack2(accB, u2, u3);
            const float r0 = tanh_fast(u0);
            const float r1 = tanh_fast(u1);
            const float r2 = tanh_fast(u2);
            const float r3 = tanh_fast(u3);

            // ---- xp for t+1 fills the tanh-latency window (h-independent).
            {
                const ULL* xn = (s < CHUNK - 1)
                    ? &xb[wip][c & 1][half][(s + 1) * FF]
                    : &xb[wip][(c + 1) & 1][half][0];
                ULL p0 = biasA, p1 = 0ULL, q0 = biasB, q1 = 0ULL;
                #pragma unroll
                for (int f = 0; f < FF; f += 2) {
                    ulonglong2 xv = *(const ulonglong2*)&xn[f];
                    p0 = ffma2(xv.x, wihA[f],     p0);
                    p1 = ffma2(xv.y, wihA[f + 1], p1);
                    q0 = ffma2(xv.x, wihB[f],     q0);
                    q1 = ffma2(xv.y, wihB[f + 1], q1);
                }
                xpA = fadd2(p0, p1);
                xpB = fadd2(q0, q1);
            }

            // ---- h writeback: intra-half-warp, same-warp smem in-order.
            ULL* hw = &hb[wip][(t + 1) & 1][half][0];
            hw[llo]      = pack2(r0, r1);
            hw[llo + 16] = pack2(r2, r3);
        }
    }

    __syncwarp();

    // ---- output head: y = h_final @ W_out^T + b_out ----
    if (llo < OO) {
        const ULL* hf = &hb[wip][0][half][0];
        float ya = b_out[llo];
        float yb = ya;
        #pragma unroll
        for (int j = 0; j < HH; ++j) {
            float ha, hc;
            unpack2(hf[j], ha, hc);
            const float wv = W_out[llo * HH + j];
            ya = fmaf(wv, ha, ya);
            yb = fmaf(wv, hc, yb);
        }
        const size_t r0 = base + 2 * half;
        out[r0 * OO + llo]       = ya;
        out[(r0 + 1) * OO + llo] = yb;
    }
}

extern "C" void kernel_launch(void* const* d_in, const int* in_sizes, int n_in,
                              void* d_out, int out_size)
{
    const float* x     = (const float*)d_in[0];
    const float* W_ih  = (const float*)d_in[1];
    const float* W_hh  = (const float*)d_in[2];
    const float* b_ih  = (const float*)d_in[3];
    const float* b_hh  = (const float*)d_in[4];
    const float* W_out = (const float*)d_in[5];
    const float* b_out = (const float*)d_in[6];
    float* out = (float*)d_out;

    // 4096 rows / (8 warps x 4 rows) = 128 blocks of 256 threads;
    // 1 block/SM, warps w and w+4 share an SMSP with engineered skew.
    rnn_fused_kernel<<<128, 32 * NW>>>(x, W_ih, W_hh, b_ih, b_hh,
                                       W_out, b_out, out);
}